// round 16
// baseline (speedup 1.0000x reference)
#include <cuda_runtime.h>
#include <cuda_fp16.h>
#include <math.h>

// ConvCaps EM routing (b=8, B=C=32, K=3, s=2, Win=13, Wout=6, 3 EM iters).
// R16: fused persistent kernel, 384 threads x 288 blocks, 2 blocks/SM
// -> 24 warps/SM (occupancy via BLOCK SIZE; grid caps blocks/SM at 2).
//  - M0 split into two d-half sweeps (R15-proven 80 regs, fits the 85 cap).
//  - read sweeps / E: R14-kBC-proven <=80 regs at 384 thr.
//  - votes computed once (M0), cached fp16 (L2-hot inside the fused kernel),
//    streamed by 4 read sweeps (depth-1 prefetch + __ldcg).
//  - R13-style red-buffer reduction (smem is plentiful); shuffle-T + global
//    atomicAdd for D; grid barrier (288 <= 296 co-resident).

#define RP0 (1.0f / 1152.0f)
#define LOG2PI 1.8378770664093453f
typedef unsigned long long ull;

__device__ float g_Wt[147456];        // [oij][q][c][p]
__device__ __half g_votes[42467328];  // [n][xy][oij][h][c][8]
__device__ float g_D0[43264];         // [n][o][13][13]
__device__ float g_D1[43264];
__device__ unsigned g_bar[2];

__global__ void prep_kernel(const float* __restrict__ W) {
    int idx = blockIdx.x * 256 + threadIdx.x;
    if (idx < 147456) {
        int p = idx & 3, c = (idx >> 2) & 31, q = (idx >> 7) & 3;
        int oij = idx >> 9;
        int o = oij / 9, ij = oij - o * 9;
        g_Wt[idx] = W[(((ij * 32 + o) * 32 + c) * 4 + p) * 4 + q];
    }
    if (idx < 43264) { g_D0[idx] = 0.0f; g_D1[idx] = 0.0f; }
    if (idx < 2) g_bar[idx] = 0u;
}

__device__ __forceinline__ ull f2fma(ull a, ull b, ull c) {
    ull d; asm("fma.rn.f32x2 %0, %1, %2, %3;" : "=l"(d) : "l"(a), "l"(b), "l"(c)); return d;
}
__device__ __forceinline__ ull f2mul(ull a, ull b) {
    ull d; asm("mul.rn.f32x2 %0, %1, %2;" : "=l"(d) : "l"(a), "l"(b)); return d;
}
__device__ __forceinline__ ull f2add(ull a, ull b) {
    ull d; asm("add.rn.f32x2 %0, %1, %2;" : "=l"(d) : "l"(a), "l"(b)); return d;
}
__device__ __forceinline__ ull f2pack(float lo, float hi) {
    ull d; asm("mov.b64 %0, {%1, %2};" : "=l"(d) : "f"(lo), "f"(hi)); return d;
}
__device__ __forceinline__ void f2unpack(float& lo, float& hi, ull v) {
    asm("mov.b64 {%0, %1}, %2;" : "=f"(lo), "=f"(hi) : "l"(v));
}
__device__ __forceinline__ unsigned f2h2(ull v) {
    float lo, hi; f2unpack(lo, hi, v);
    unsigned r; asm("cvt.rn.f16x2.f32 %0, %1, %2;" : "=r"(r) : "f"(hi), "f"(lo));
    return r;
}
__device__ __forceinline__ ull h2w(unsigned u) {
    __half2 h = *reinterpret_cast<__half2*>(&u);
    float2 f = __half22float2(h);
    return f2pack(f.x, f.y);
}

// smem float offsets (total 24096 floats = 96384 B; 2 blocks/SM fits 228KB)
#define SM_PH   0        // 9216: pose2 [oij][qr][2] during M0; ph [oij][c] after
#define SM_A    9216     // 288
#define SM_AD   9504     // 288
#define SM_RED  9792     // [w][c][33] : 12*1056 = 12672
#define SM_MOM  22464    // [c][33] : 1056
#define SM_MU   23520    // [c][17] : 544
#define SM_SFAC 24064    // 32
#define SMEM_FLOATS 24096

__global__ void __launch_bounds__(384, 2) fused_kernel(
    const float* __restrict__ x,
    const float* __restrict__ bv_p,
    const float* __restrict__ ba_p,
    const float* __restrict__ lam_p,
    float* __restrict__ out)
{
    extern __shared__ float sm[];
    float* pose2  = sm + SM_PH;     // M0 only
    float* ph_s   = sm + SM_PH;     // alias: born in E0 (pose dead)
    float* a_s    = sm + SM_A;
    float* aD_s   = sm + SM_AD;
    float* red    = sm + SM_RED;
    float* mom    = sm + SM_MOM;
    float* mu_s   = sm + SM_MU;
    float* sfac_s = sm + SM_SFAC;

    const int xy = blockIdx.x, n = blockIdx.y;
    const int X = xy / 6, Y = xy % 6;
    const int tid = threadIdx.x;
    const int w = tid >> 5;         // warp 0..11 -> positions w*24 .. w*24+23
    const int c = tid & 31;
    const float* xn = x + n * (544 * 169);
    const int base = (2 * X) * 13 + 2 * Y;

    // ---- load patch ----
    for (int e = tid; e < 512; e += 384) {
        int qr = e & 15, o = e >> 4;
        const float* src = xn + (qr * 32 + o) * 169 + base;
        #pragma unroll
        for (int i = 0; i < 3; i++)
            #pragma unroll
            for (int j = 0; j < 3; j++) {
                float v = src[i * 13 + j];
                int off = (o * 9 + i * 3 + j) * 32 + qr * 2;
                pose2[off] = v; pose2[off + 1] = v;
            }
    }
    if (tid < 288) {
        int o = tid / 9, ij = tid - o * 9;
        float av = xn[(512 + o) * 169 + base + (ij / 3) * 13 + (ij % 3)];
        a_s[tid] = av;
        aD_s[tid] = av * RP0;
    }
    __syncthreads();

    const float bv = bv_p[0], ba = ba_p[0], lam = lam_p[0];
    uint4* vb = (uint4*)g_votes + (((n * 36 + xy) * 288 + w * 24) * 2) * 32 + c;
    const ull* wbh = (const ull*)g_Wt + (w * 24 * 4) * 64 + c * 2;   // + h

    for (int it = 0; it < 3; it++) {
        float* myred = red + (w * 32 + c) * 33;

        if (it == 0) {
            // ====== M0: two d-half sweeps (80 regs proven) ======
            #pragma unroll 1
            for (int h = 0; h < 2; h++) {
                ull m1[4], m2[4];
                #pragma unroll
                for (int r = 0; r < 4; r++) { m1[r] = 0ull; m2[r] = 0ull; }
                float sumr = 0.0f;
                #pragma unroll 2
                for (int k = 0; k < 24; k++) {
                    int oij = w * 24 + k;
                    const ull* wk = wbh + (k * 4) * 64 + h;
                    ull wq0 = wk[0], wq1 = wk[64], wq2 = wk[128], wq3 = wk[192];
                    float rh = aD_s[oij];
                    sumr += rh;
                    ull rh2 = f2pack(rh, rh);
                    const ulonglong2* pb2 = (const ulonglong2*)(pose2 + oij * 32);
                    ull v[4];
                    {
                        ulonglong2 pA = pb2[0], pB = pb2[1];
                        v[0] = f2mul(wq0, pA.x); v[1] = f2mul(wq0, pA.y);
                        v[2] = f2mul(wq0, pB.x); v[3] = f2mul(wq0, pB.y);
                    }
                    {
                        ulonglong2 pA = pb2[2], pB = pb2[3];
                        v[0] = f2fma(wq1, pA.x, v[0]); v[1] = f2fma(wq1, pA.y, v[1]);
                        v[2] = f2fma(wq1, pB.x, v[2]); v[3] = f2fma(wq1, pB.y, v[3]);
                    }
                    {
                        ulonglong2 pA = pb2[4], pB = pb2[5];
                        v[0] = f2fma(wq2, pA.x, v[0]); v[1] = f2fma(wq2, pA.y, v[1]);
                        v[2] = f2fma(wq2, pB.x, v[2]); v[3] = f2fma(wq2, pB.y, v[3]);
                    }
                    {
                        ulonglong2 pA = pb2[6], pB = pb2[7];
                        v[0] = f2fma(wq3, pA.x, v[0]); v[1] = f2fma(wq3, pA.y, v[1]);
                        v[2] = f2fma(wq3, pB.x, v[2]); v[3] = f2fma(wq3, pB.y, v[3]);
                    }
                    uint4 s4;
                    s4.x = f2h2(v[0]); s4.y = f2h2(v[1]);
                    s4.z = f2h2(v[2]); s4.w = f2h2(v[3]);
                    vb[k * 64 + h * 32] = s4;
                    #pragma unroll
                    for (int r = 0; r < 4; r++) {
                        ull t = f2mul(rh2, v[r]);
                        m1[r] = f2add(m1[r], t);
                        m2[r] = f2fma(t, v[r], m2[r]);
                    }
                }
                // red slots: d = 8h + {r, 4+r}
                #pragma unroll
                for (int r = 0; r < 4; r++) {
                    float lo, hi;
                    f2unpack(lo, hi, m1[r]);
                    myred[8 * h + r] = lo; myred[8 * h + 4 + r] = hi;
                    f2unpack(lo, hi, m2[r]);
                    myred[16 + 8 * h + r] = lo; myred[16 + 8 * h + 4 + r] = hi;
                }
                if (h == 0) myred[32] = sumr;
            }
        } else {
            // ====== M-read: stream cached votes ======
            ull m1a[4], m1b[4], m2a[4], m2b[4];
            #pragma unroll
            for (int r = 0; r < 4; r++) { m1a[r]=0ull; m1b[r]=0ull; m2a[r]=0ull; m2b[r]=0ull; }
            float sumr = 0.0f;
            uint4 a0 = __ldcg(vb), a1 = __ldcg(vb + 32);
            #pragma unroll 4
            for (int k = 0; k < 24; k++) {
                uint4 b0 = a0, b1 = a1;
                if (k < 23) { b0 = __ldcg(vb + (k + 1) * 64); b1 = __ldcg(vb + (k + 1) * 64 + 32); }
                int oij = w * 24 + k;
                float rh = ph_s[oij * 32 + c] * aD_s[oij];
                sumr += rh;
                ull rh2 = f2pack(rh, rh);
                ull sv0[4], sv1[4];
                sv0[0] = h2w(a0.x); sv0[1] = h2w(a0.y); sv0[2] = h2w(a0.z); sv0[3] = h2w(a0.w);
                sv1[0] = h2w(a1.x); sv1[1] = h2w(a1.y); sv1[2] = h2w(a1.z); sv1[3] = h2w(a1.w);
                #pragma unroll
                for (int r = 0; r < 4; r++) {
                    ull t0 = f2mul(rh2, sv0[r]);
                    m1a[r] = f2add(m1a[r], t0);
                    m2a[r] = f2fma(t0, sv0[r], m2a[r]);
                    ull t1 = f2mul(rh2, sv1[r]);
                    m1b[r] = f2add(m1b[r], t1);
                    m2b[r] = f2fma(t1, sv1[r], m2b[r]);
                }
                a0 = b0; a1 = b1;
            }
            // red slots: halves h=0 (sv0: d 0..7), h=1 (sv1: d 8..15)
            #pragma unroll
            for (int r = 0; r < 4; r++) {
                float lo, hi;
                f2unpack(lo, hi, m1a[r]); myred[r]      = lo; myred[4 + r]  = hi;
                f2unpack(lo, hi, m1b[r]); myred[8 + r]  = lo; myred[12 + r] = hi;
                f2unpack(lo, hi, m2a[r]); myred[16 + r] = lo; myred[20 + r] = hi;
                f2unpack(lo, hi, m2b[r]); myred[24 + r] = lo; myred[28 + r] = hi;
            }
            myred[32] = sumr;
        }
        __syncthreads();

        // ---- gather reduction over 12 warps ----
        for (int s = tid; s < 1056; s += 384) {
            float acc = 0.0f;
            #pragma unroll
            for (int ww = 0; ww < 12; ww++) acc += red[ww * 1056 + s];
            mom[s] = acc;
        }
        __syncthreads();

        // ================= stats =================
        if (tid < 32) {
            const float* mm = mom + tid * 33;
            float R = mm[32], invR = 1.0f / R, cs = 0.0f;
            #pragma unroll
            for (int d = 0; d < 16; d++) {
                float m  = mm[d] * invR;
                float sg = fmaf(-m, m, mm[16 + d] * invR);
                mu_s[tid * 17 + d] = m;
                cs += __logf(sg);
            }
            float cost = R * fmaf(16.0f, bv, cs);
            float act  = 1.0f / (1.0f + __expf(lam * (cost - ba)));
            if (it == 2) {
                float* on = out + (long)n * 19584 + xy;
                #pragma unroll
                for (int d = 0; d < 16; d++)
                    on[(tid * 16 + d) * 36] = mu_s[tid * 17 + d];
                on[(512 + tid) * 36] = act;
            } else {
                sfac_s[tid] = act * __expf(-0.5f * fmaf(16.0f, LOG2PI, cs));
            }
        }
        if (it == 2) return;
        __syncthreads();

        // ====== E: stream votes; ph -> smem (overwrites dead pose2); D atomic ======
        {
            float sf = sfac_s[c];
            ull nmu0[4], nmu1[4];
            #pragma unroll
            for (int r = 0; r < 4; r++) {
                nmu0[r] = f2pack(-mu_s[c * 17 + r],     -mu_s[c * 17 + 4 + r]);
                nmu1[r] = f2pack(-mu_s[c * 17 + 8 + r], -mu_s[c * 17 + 12 + r]);
            }
            float* Dg = (it == 0) ? g_D0 : g_D1;
            uint4 a0 = __ldcg(vb), a1 = __ldcg(vb + 32);
            #pragma unroll 4
            for (int k = 0; k < 24; k++) {
                uint4 b0 = a0, b1 = a1;
                if (k < 23) { b0 = __ldcg(vb + (k + 1) * 64); b1 = __ldcg(vb + (k + 1) * 64 + 32); }
                int oij = w * 24 + k;
                ull sa, sb;
                { ull d0 = f2add(h2w(a0.x), nmu0[0]); sa = f2mul(d0, d0);
                  ull d1 = f2add(h2w(a0.y), nmu0[1]); sb = f2mul(d1, d1); }
                { ull d0 = f2add(h2w(a0.z), nmu0[2]); sa = f2fma(d0, d0, sa);
                  ull d1 = f2add(h2w(a0.w), nmu0[3]); sb = f2fma(d1, d1, sb); }
                { ull d0 = f2add(h2w(a1.x), nmu1[0]); sa = f2fma(d0, d0, sa);
                  ull d1 = f2add(h2w(a1.y), nmu1[1]); sb = f2fma(d1, d1, sb); }
                { ull d0 = f2add(h2w(a1.z), nmu1[2]); sa = f2fma(d0, d0, sa);
                  ull d1 = f2add(h2w(a1.w), nmu1[3]); sb = f2fma(d1, d1, sb); }
                float slo, shi; f2unpack(slo, shi, f2add(sa, sb));
                float ph = sf * __expf(-(slo + shi));
                // kperm=[0,2,1] self-inverse: file p_hat at permuted slot
                int o = oij / 9, ij = oij - o * 9;
                int i2 = ij / 3, j2 = ij - i2 * 3;
                int ip = (3 - i2) % 3, jp = (3 - j2) % 3;
                ph_s[(o * 9 + ip * 3 + jp) * 32 + c] = ph;
                float T = ph;
                #pragma unroll
                for (int s = 16; s > 0; s >>= 1) T += __shfl_xor_sync(0xffffffffu, T, s);
                if (c == 0)
                    atomicAdd(&Dg[(n * 32 + o) * 169 + (2 * X + ip) * 13 + (2 * Y + jp)], T);
                a0 = b0; a1 = b1;
            }
        }
        __syncthreads();

        // ---- grid barrier (288 blocks, 2/SM co-resident: 296 slots) ----
        if (tid == 0) {
            __threadfence();
            atomicAdd(&g_bar[it], 1u);
            while (*((volatile unsigned*)&g_bar[it]) < 288u) { __nanosleep(32); }
        }
        __syncthreads();

        // ---- aD pass ----
        if (tid < 288) {
            int o = tid / 9, ij = tid - o * 9;
            float* Dg = (it == 0) ? g_D0 : g_D1;
            float Dv = __ldcg(&Dg[(n * 32 + o) * 169 + (2 * X + ij / 3) * 13 + (2 * Y + ij % 3)]);
            aD_s[tid] = __fdividef(a_s[tid], Dv);
        }
        __syncthreads();
    }
}

extern "C" void kernel_launch(void* const* d_in, const int* in_sizes, int n_in,
                              void* d_out, int out_size) {
    const float* x   = (const float*)d_in[0];
    const float* W   = (const float*)d_in[1];
    const float* bv  = (const float*)d_in[2];
    const float* ba  = (const float*)d_in[3];
    const float* lam = (const float*)d_in[4];
    float* out = (float*)d_out;

    const int smem = SMEM_FLOATS * 4;   // 96384 B
    cudaFuncSetAttribute(fused_kernel, cudaFuncAttributeMaxDynamicSharedMemorySize, smem);

    prep_kernel<<<576, 256>>>(W);
    fused_kernel<<<dim3(36, 8), 384, smem>>>(x, bv, ba, lam, out);
}

// round 17
// speedup vs baseline: 1.8599x; 1.8599x over previous
#include <cuda_runtime.h>
#include <cuda_fp16.h>
#include <math.h>

// ConvCaps EM routing (b=8, B=C=32, K=3, s=2, Win=13, Wout=6, 3 EM iters).
// R17 = R13 (best measured: 74.2us) with M0 W-prefetch removed (measured
// neutral, frees regs off the 128 hard cap -> avoids marginal spill risk).
// Design: fused persistent kernel, 256 thr, 2 blk/SM; votes computed once in
// M0 (fp32 pose x W, packed f32x2), cached fp16 in an 85MB L2-resident
// buffer; 4 read sweeps stream it back (depth-2 prefetch + __ldcg).
// p_hat block-local in smem; grid barrier only for the D normalizer.

#define RP0 (1.0f / 1152.0f)
#define LOG2PI 1.8378770664093453f
typedef unsigned long long ull;

__device__ float g_Wt[147456];        // [o][ij][q][c][p]  (ulonglong2 per (q,c))
__device__ __half g_votes[42467328];  // [n][xy][oij][g][c][8]  85 MB
__device__ float g_D0[43264];         // [n][o][13][13]
__device__ float g_D1[43264];
__device__ unsigned g_bar[2];

__global__ void prep_kernel(const float* __restrict__ W) {
    int idx = blockIdx.x * 256 + threadIdx.x;
    if (idx < 147456) {
        int p = idx & 3, c = (idx >> 2) & 31, q = (idx >> 7) & 3;
        int oij = idx >> 9;
        int o = oij / 9, ij = oij - o * 9;
        // src: W[i,j,o,c,p,q]
        g_Wt[idx] = W[(((ij * 32 + o) * 32 + c) * 4 + p) * 4 + q];
    }
    if (idx < 43264) { g_D0[idx] = 0.0f; g_D1[idx] = 0.0f; }
    if (idx < 2) g_bar[idx] = 0u;
}

__device__ __forceinline__ ull f2fma(ull a, ull b, ull c) {
    ull d; asm("fma.rn.f32x2 %0, %1, %2, %3;" : "=l"(d) : "l"(a), "l"(b), "l"(c)); return d;
}
__device__ __forceinline__ ull f2mul(ull a, ull b) {
    ull d; asm("mul.rn.f32x2 %0, %1, %2;" : "=l"(d) : "l"(a), "l"(b)); return d;
}
__device__ __forceinline__ ull f2add(ull a, ull b) {
    ull d; asm("add.rn.f32x2 %0, %1, %2;" : "=l"(d) : "l"(a), "l"(b)); return d;
}
__device__ __forceinline__ ull f2pack(float lo, float hi) {
    ull d; asm("mov.b64 %0, {%1, %2};" : "=l"(d) : "f"(lo), "f"(hi)); return d;
}
__device__ __forceinline__ void f2unpack(float& lo, float& hi, ull v) {
    asm("mov.b64 {%0, %1}, %2;" : "=f"(lo), "=f"(hi) : "l"(v));
}
__device__ __forceinline__ unsigned f2h2(ull v) {    // packed f32x2 -> half2
    float lo, hi; f2unpack(lo, hi, v);
    unsigned r; asm("cvt.rn.f16x2.f32 %0, %1, %2;" : "=r"(r) : "f"(hi), "f"(lo));
    return r;
}
__device__ __forceinline__ ull h2w(unsigned u) {     // half2 -> packed f32x2
    __half2 h = *reinterpret_cast<__half2*>(&u);
    float2 f = __half22float2(h);
    return f2pack(f.x, f.y);
}

// smem float offsets
#define SM_POSE2 0        // [oij][qr][2] duplicated pose: 9216
#define SM_A     9216     // 288
#define SM_AD    9504     // 288
#define SM_PH    9792     // [oij][33] p_hat (red 8*1056=8448 aliased): 9504
#define SM_MOM   19296    // [c][33]: 1056
#define SM_MU    20352    // [c][17]: 544
#define SM_SFAC  20896    // 32
#define SMEM_FLOATS 20928

__global__ void __launch_bounds__(256, 2) fused_kernel(
    const float* __restrict__ x,
    const float* __restrict__ bv_p,
    const float* __restrict__ ba_p,
    const float* __restrict__ lam_p,
    float* __restrict__ out)
{
    extern __shared__ float sm[];
    float* pose2  = sm + SM_POSE2;
    float* a_s    = sm + SM_A;
    float* aD_s   = sm + SM_AD;
    float* ph_s   = sm + SM_PH;
    float* red    = ph_s;          // aliased: red live only between M and stats
    float* mom    = sm + SM_MOM;
    float* mu_s   = sm + SM_MU;
    float* sfac_s = sm + SM_SFAC;

    const int xy = blockIdx.x;     // 0..35
    const int n  = blockIdx.y;     // 0..7
    const int X = xy / 6, Y = xy % 6;
    const int tid = threadIdx.x;
    const int w = tid >> 5;        // warp 0..7 -> positions w*36 .. w*36+35
    const int c = tid & 31;        // lane = output capsule

    const float* xn = x + n * (544 * 169);
    const int base = (2 * X) * 13 + 2 * Y;

    // ---- load patch: duplicated pose (qr-inner), act ----
    for (int e = tid; e < 512; e += 256) {
        int qr = e & 15, o = e >> 4;
        const float* src = xn + (qr * 32 + o) * 169 + base;
        #pragma unroll
        for (int i = 0; i < 3; i++)
            #pragma unroll
            for (int j = 0; j < 3; j++) {
                float v = src[i * 13 + j];
                int off = (o * 9 + i * 3 + j) * 32 + qr * 2;
                pose2[off] = v; pose2[off + 1] = v;
            }
    }
    for (int e = tid; e < 288; e += 256) {
        int o = e / 9, ij = e - o * 9;
        float av = xn[(512 + o) * 169 + base + (ij / 3) * 13 + (ij % 3)];
        a_s[e] = av;
        aD_s[e] = av * RP0;        // iter0: rh = ph(=1) * aD
    }
    for (int e = tid; e < 9504; e += 256) ph_s[e] = 1.0f;
    __syncthreads();

    const float bv = bv_p[0], ba = ba_p[0], lam = lam_p[0];
    const ulonglong2* wbase = (const ulonglong2*)g_Wt + (w * 36 * 4) * 32 + c;
    uint4* vb = (uint4*)g_votes + (((n * 36 + xy) * 288 + w * 36) * 2) * 32 + c;

    for (int it = 0; it < 3; it++) {
        // ================= M phase =================
        ull m1a[4], m1b[4], m2a[4], m2b[4];
        #pragma unroll
        for (int r = 0; r < 4; r++) { m1a[r]=0ull; m1b[r]=0ull; m2a[r]=0ull; m2b[r]=0ull; }
        float sumr = 0.0f;

        if (it == 0) {
            // ---- M0: compute votes from pose x W, store fp16, moments ----
            #pragma unroll 2
            for (int k = 0; k < 36; k++) {
                int oij = w * 36 + k;
                const ulonglong2* wp = wbase + k * 128;
                ulonglong2 wv0 = wp[0], wv1 = wp[32], wv2 = wp[64], wv3 = wp[96];
                float rh = aD_s[oij];
                sumr += rh;
                ull rh2 = f2pack(rh, rh);
                const ulonglong2* pb2 = (const ulonglong2*)(pose2 + oij * 32);
                ull v0[4], v1[4];
                {
                    ulonglong2 pA = pb2[0], pB = pb2[1];   // q=0: dup P r0..r3
                    v0[0] = f2mul(wv0.x, pA.x); v1[0] = f2mul(wv0.y, pA.x);
                    v0[1] = f2mul(wv0.x, pA.y); v1[1] = f2mul(wv0.y, pA.y);
                    v0[2] = f2mul(wv0.x, pB.x); v1[2] = f2mul(wv0.y, pB.x);
                    v0[3] = f2mul(wv0.x, pB.y); v1[3] = f2mul(wv0.y, pB.y);
                }
                {
                    ulonglong2 pA = pb2[2], pB = pb2[3];
                    v0[0] = f2fma(wv1.x, pA.x, v0[0]); v1[0] = f2fma(wv1.y, pA.x, v1[0]);
                    v0[1] = f2fma(wv1.x, pA.y, v0[1]); v1[1] = f2fma(wv1.y, pA.y, v1[1]);
                    v0[2] = f2fma(wv1.x, pB.x, v0[2]); v1[2] = f2fma(wv1.y, pB.x, v1[2]);
                    v0[3] = f2fma(wv1.x, pB.y, v0[3]); v1[3] = f2fma(wv1.y, pB.y, v1[3]);
                }
                {
                    ulonglong2 pA = pb2[4], pB = pb2[5];
                    v0[0] = f2fma(wv2.x, pA.x, v0[0]); v1[0] = f2fma(wv2.y, pA.x, v1[0]);
                    v0[1] = f2fma(wv2.x, pA.y, v0[1]); v1[1] = f2fma(wv2.y, pA.y, v1[1]);
                    v0[2] = f2fma(wv2.x, pB.x, v0[2]); v1[2] = f2fma(wv2.y, pB.x, v1[2]);
                    v0[3] = f2fma(wv2.x, pB.y, v0[3]); v1[3] = f2fma(wv2.y, pB.y, v1[3]);
                }
                {
                    ulonglong2 pA = pb2[6], pB = pb2[7];
                    v0[0] = f2fma(wv3.x, pA.x, v0[0]); v1[0] = f2fma(wv3.y, pA.x, v1[0]);
                    v0[1] = f2fma(wv3.x, pA.y, v0[1]); v1[1] = f2fma(wv3.y, pA.y, v1[1]);
                    v0[2] = f2fma(wv3.x, pB.x, v0[2]); v1[2] = f2fma(wv3.y, pB.x, v1[2]);
                    v0[3] = f2fma(wv3.x, pB.y, v0[3]); v1[3] = f2fma(wv3.y, pB.y, v1[3]);
                }
                uint4 s0, s1;
                s0.x = f2h2(v0[0]); s0.y = f2h2(v0[1]); s0.z = f2h2(v0[2]); s0.w = f2h2(v0[3]);
                s1.x = f2h2(v1[0]); s1.y = f2h2(v1[1]); s1.z = f2h2(v1[2]); s1.w = f2h2(v1[3]);
                vb[k * 64] = s0; vb[k * 64 + 32] = s1;
                #pragma unroll
                for (int r = 0; r < 4; r++) {
                    ull t0 = f2mul(rh2, v0[r]);
                    m1a[r] = f2add(m1a[r], t0);
                    m2a[r] = f2fma(t0, v0[r], m2a[r]);
                    ull t1 = f2mul(rh2, v1[r]);
                    m1b[r] = f2add(m1b[r], t1);
                    m2b[r] = f2fma(t1, v1[r], m2b[r]);
                }
            }
        } else {
            // ---- M-read: stream cached votes (depth-2 prefetch), moments ----
            uint4 a0 = __ldcg(vb), a1 = __ldcg(vb + 32);
            uint4 b0 = __ldcg(vb + 64), b1 = __ldcg(vb + 96);
            #pragma unroll 4
            for (int k = 0; k < 36; k++) {
                uint4 c0 = b0, c1 = b1;
                if (k < 34) { c0 = __ldcg(vb + (k + 2) * 64); c1 = __ldcg(vb + (k + 2) * 64 + 32); }
                int oij = w * 36 + k;
                float rh = ph_s[oij * 33 + c] * aD_s[oij];
                sumr += rh;
                ull rh2 = f2pack(rh, rh);
                ull sv0[4], sv1[4];
                sv0[0] = h2w(a0.x); sv0[1] = h2w(a0.y); sv0[2] = h2w(a0.z); sv0[3] = h2w(a0.w);
                sv1[0] = h2w(a1.x); sv1[1] = h2w(a1.y); sv1[2] = h2w(a1.z); sv1[3] = h2w(a1.w);
                #pragma unroll
                for (int r = 0; r < 4; r++) {
                    ull t0 = f2mul(rh2, sv0[r]);
                    m1a[r] = f2add(m1a[r], t0);
                    m2a[r] = f2fma(t0, sv0[r], m2a[r]);
                    ull t1 = f2mul(rh2, sv1[r]);
                    m1b[r] = f2add(m1b[r], t1);
                    m2b[r] = f2fma(t1, sv1[r], m2b[r]);
                }
                a0 = b0; a1 = b1; b0 = c0; b1 = c1;
            }
        }
        __syncthreads();   // all ph reads done before red overwrites it

        // pair layout: v0[r] = (d=r, d=4+r), v1[r] = (d=8+r, d=12+r)
        {
            float* myred = red + (w * 32 + c) * 33;
            #pragma unroll
            for (int r = 0; r < 4; r++) {
                float lo, hi;
                f2unpack(lo, hi, m1a[r]); myred[r]      = lo; myred[4 + r]  = hi;
                f2unpack(lo, hi, m1b[r]); myred[8 + r]  = lo; myred[12 + r] = hi;
                f2unpack(lo, hi, m2a[r]); myred[16 + r] = lo; myred[20 + r] = hi;
                f2unpack(lo, hi, m2b[r]); myred[24 + r] = lo; myred[28 + r] = hi;
            }
            myred[32] = sumr;
        }
        __syncthreads();
        for (int s = tid; s < 1056; s += 256) {
            float acc = 0.0f;
            #pragma unroll
            for (int ww = 0; ww < 8; ww++) acc += red[ww * 1056 + s];
            mom[s] = acc;
        }
        __syncthreads();

        // ================= stats =================
        if (tid < 32) {
            const float* mm = mom + tid * 33;
            float R = mm[32];
            float invR = 1.0f / R;
            float cs = 0.0f;
            #pragma unroll
            for (int d = 0; d < 16; d++) {
                float m  = mm[d] * invR;
                float sg = fmaf(-m, m, mm[16 + d] * invR);
                mu_s[tid * 17 + d] = m;
                cs += __logf(sg);
            }
            float cost = R * fmaf(16.0f, bv, cs);
            float act  = 1.0f / (1.0f + __expf(lam * (cost - ba)));
            if (it == 2) {
                float* on = out + (long)n * 19584 + xy;
                #pragma unroll
                for (int d = 0; d < 16; d++)
                    on[(tid * 16 + d) * 36] = mu_s[tid * 17 + d];
                on[(512 + tid) * 36] = act;
            } else {
                sfac_s[tid] = act * __expf(-0.5f * fmaf(16.0f, LOG2PI, cs));
            }
        }
        __syncthreads();
        if (it == 2) return;

        // ====== E phase: stream cached votes (depth-2 prefetch) ======
        {
            float sf = sfac_s[c];
            ull nmu0[4], nmu1[4];
            #pragma unroll
            for (int r = 0; r < 4; r++) {
                nmu0[r] = f2pack(-mu_s[c * 17 + r],     -mu_s[c * 17 + 4 + r]);
                nmu1[r] = f2pack(-mu_s[c * 17 + 8 + r], -mu_s[c * 17 + 12 + r]);
            }
            uint4 a0 = __ldcg(vb), a1 = __ldcg(vb + 32);
            uint4 b0 = __ldcg(vb + 64), b1 = __ldcg(vb + 96);
            #pragma unroll 4
            for (int k = 0; k < 36; k++) {
                uint4 c0 = b0, c1 = b1;
                if (k < 34) { c0 = __ldcg(vb + (k + 2) * 64); c1 = __ldcg(vb + (k + 2) * 64 + 32); }
                int oij = w * 36 + k;
                // dual ssd chains
                ull sa, sb;
                {
                    ull d0 = f2add(h2w(a0.x), nmu0[0]); sa = f2mul(d0, d0);
                    ull d1 = f2add(h2w(a0.y), nmu0[1]); sb = f2mul(d1, d1);
                }
                {
                    ull d0 = f2add(h2w(a0.z), nmu0[2]); sa = f2fma(d0, d0, sa);
                    ull d1 = f2add(h2w(a0.w), nmu0[3]); sb = f2fma(d1, d1, sb);
                }
                {
                    ull d0 = f2add(h2w(a1.x), nmu1[0]); sa = f2fma(d0, d0, sa);
                    ull d1 = f2add(h2w(a1.y), nmu1[1]); sb = f2fma(d1, d1, sb);
                }
                {
                    ull d0 = f2add(h2w(a1.z), nmu1[2]); sa = f2fma(d0, d0, sa);
                    ull d1 = f2add(h2w(a1.w), nmu1[3]); sb = f2fma(d1, d1, sb);
                }
                ull ssd2 = f2add(sa, sb);
                float slo, shi; f2unpack(slo, shi, ssd2);
                float ph = sf * __expf(-(slo + shi));
                // kperm=[0,2,1] self-inverse: file p_hat at permuted slot
                int o = oij / 9, ij = oij - o * 9;
                int i2 = ij / 3, j2 = ij - i2 * 3;
                ph_s[(o * 9 + ((3 - i2) % 3) * 3 + ((3 - j2) % 3)) * 33 + c] = ph;
                a0 = b0; a1 = b1; b0 = c0; b1 = c1;
            }
        }
        __syncthreads();

        // ---- D pass: row sums -> global atomics ----
        float* Dg = (it == 0) ? g_D0 : g_D1;
        for (int row = tid; row < 288; row += 256) {
            const float* pr = ph_s + row * 33;
            float s = 0.0f;
            #pragma unroll
            for (int k = 0; k < 32; k++) s += pr[k];
            int o = row / 9, ij = row - o * 9;
            atomicAdd(&Dg[(n * 32 + o) * 169 + (2 * X + ij / 3) * 13 + (2 * Y + ij % 3)], s);
        }

        // ---- grid barrier (288 blocks, 2/SM provably co-resident) ----
        __syncthreads();
        if (tid == 0) {
            __threadfence();
            atomicAdd(&g_bar[it], 1u);
            while (*((volatile unsigned*)&g_bar[it]) < 288u) { __nanosleep(32); }
        }
        __syncthreads();

        // ---- aD pass: a / D ----
        for (int e = tid; e < 288; e += 256) {
            int o = e / 9, ij = e - o * 9;
            float Dv = __ldcg(&Dg[(n * 32 + o) * 169 + (2 * X + ij / 3) * 13 + (2 * Y + ij % 3)]);
            aD_s[e] = __fdividef(a_s[e], Dv);
        }
        __syncthreads();
    }
}

extern "C" void kernel_launch(void* const* d_in, const int* in_sizes, int n_in,
                              void* d_out, int out_size) {
    const float* x   = (const float*)d_in[0];
    const float* W   = (const float*)d_in[1];
    const float* bv  = (const float*)d_in[2];
    const float* ba  = (const float*)d_in[3];
    const float* lam = (const float*)d_in[4];
    float* out = (float*)d_out;

    const int smem = SMEM_FLOATS * 4;   // 83712 B
    cudaFuncSetAttribute(fused_kernel, cudaFuncAttributeMaxDynamicSharedMemorySize, smem);

    prep_kernel<<<576, 256>>>(W);
    fused_kernel<<<dim3(36, 8), 256, smem>>>(x, bv, ba, lam, out);
}